// round 1
// baseline (speedup 1.0000x reference)
#include <cuda_runtime.h>

// Problem constants (fixed by the reference).
#define BB 2
#define TT 2048
#define CC 1024
#define NH 16
#define HS 64

// Scratch (allocation-free rule: __device__ globals).
// g_S: attention scores / probabilities, [B, NH, T, T]  = 512 MB
// g_Z: per-head projected values  Z[h, b*T + s, c] = x[b] @ W_h, [NH, B*T, C] = 256 MB
__device__ float g_S[134217728];  // 2*16*2048*2048
__device__ float g_Z[67108864];   // 16*2*2048*1024

// ---------------------------------------------------------------------------
// Shared micro-kernel: 128x128 block tile, 256 threads, 8x8 per-thread tile.
// Warp layout: 8 warps as 4 (rows) x 2 (cols); warp tile 32x64.
// Lane layout: ar = (lane>>3)*4 row offset, bc = (lane&7)*4 col offset.
// Thread owns rows {wr+ar+0..3, wr+ar+16..19}, cols {wc+bc+0..3, wc+bc+32..35}
// -> all smem fragment loads are conflict-free / broadcast float4.
// ---------------------------------------------------------------------------
__device__ __forceinline__ void mma_step(const float (*Ash)[128],
                                         const float (*Bsh)[128],
                                         int wr, int wc, int ar, int bc,
                                         float acc[8][8]) {
#pragma unroll
    for (int k = 0; k < 8; ++k) {
        float4 a0 = *(const float4*)&Ash[k][wr + ar];
        float4 a1 = *(const float4*)&Ash[k][wr + 16 + ar];
        float4 b0 = *(const float4*)&Bsh[k][wc + bc];
        float4 b1 = *(const float4*)&Bsh[k][wc + 32 + bc];
        float av[8] = {a0.x, a0.y, a0.z, a0.w, a1.x, a1.y, a1.z, a1.w};
        float bv[8] = {b0.x, b0.y, b0.z, b0.w, b1.x, b1.y, b1.z, b1.w};
#pragma unroll
        for (int i = 0; i < 8; ++i)
#pragma unroll
            for (int j = 0; j < 8; ++j)
                acc[i][j] = fmaf(av[i], bv[j], acc[i][j]);
    }
}

// ---------------------------------------------------------------------------
// Kernel 1: scores  S[b,h,t,s] = (y_t . y_s) / 8   (NT GEMM, K = 64)
// y[b,t,h,:] = x[b, t, h*64 : (h+1)*64]
// ---------------------------------------------------------------------------
__global__ __launch_bounds__(256, 2) void scores_kernel(const float* __restrict__ x) {
    const int bh   = blockIdx.z;            // b*16 + h
    const int b    = bh >> 4;
    const int h    = bh & 15;
    const int row0 = blockIdx.y * 128;      // t tile
    const int col0 = blockIdx.x * 128;      // s tile

    const float* Ab = x + ((size_t)(b * TT + row0)) * CC + h * HS;
    const float* Bb = x + ((size_t)(b * TT + col0)) * CC + h * HS;

    __shared__ float As[2][8][128];
    __shared__ float Bs[2][8][128];

    const int tid  = threadIdx.x;
    const int ldr  = tid >> 1;              // 0..127 (tile row)
    const int ldk  = (tid & 1) * 4;         // 0 or 4 (k offset)
    const int warp = tid >> 5, lane = tid & 31;
    const int wr = (warp & 3) * 32, wc = (warp >> 2) * 64;
    const int ar = (lane >> 3) * 4, bc = (lane & 7) * 4;

    float acc[8][8];
#pragma unroll
    for (int i = 0; i < 8; ++i)
#pragma unroll
        for (int j = 0; j < 8; ++j) acc[i][j] = 0.f;

    // prologue: k-tile 0
    {
        float4 a4 = *(const float4*)(Ab + (size_t)ldr * CC + ldk);
        float4 b4 = *(const float4*)(Bb + (size_t)ldr * CC + ldk);
        As[0][ldk + 0][ldr] = a4.x; As[0][ldk + 1][ldr] = a4.y;
        As[0][ldk + 2][ldr] = a4.z; As[0][ldk + 3][ldr] = a4.w;
        Bs[0][ldk + 0][ldr] = b4.x; Bs[0][ldk + 1][ldr] = b4.y;
        Bs[0][ldk + 2][ldr] = b4.z; Bs[0][ldk + 3][ldr] = b4.w;
    }
    __syncthreads();

    int buf = 0;
    const int NK = HS / 8;  // 8
    for (int kt = 0; kt < NK; ++kt) {
        float4 a4n, b4n;
        if (kt + 1 < NK) {
            a4n = *(const float4*)(Ab + (size_t)ldr * CC + (kt + 1) * 8 + ldk);
            b4n = *(const float4*)(Bb + (size_t)ldr * CC + (kt + 1) * 8 + ldk);
        }
        mma_step(As[buf], Bs[buf], wr, wc, ar, bc, acc);
        if (kt + 1 < NK) {
            const int nb = buf ^ 1;
            As[nb][ldk + 0][ldr] = a4n.x; As[nb][ldk + 1][ldr] = a4n.y;
            As[nb][ldk + 2][ldr] = a4n.z; As[nb][ldk + 3][ldr] = a4n.w;
            Bs[nb][ldk + 0][ldr] = b4n.x; Bs[nb][ldk + 1][ldr] = b4n.y;
            Bs[nb][ldk + 2][ldr] = b4n.z; Bs[nb][ldk + 3][ldr] = b4n.w;
            __syncthreads();
            buf = nb;
        }
    }

    // epilogue: scale by 1/sqrt(64) = 0.125
#pragma unroll
    for (int i = 0; i < 8; ++i) {
        const int r = wr + ar + (i < 4 ? i : i + 12);
        float* cp = g_S + ((size_t)bh * TT + row0 + r) * TT + col0 + wc;
        *(float4*)(cp + bc) = make_float4(acc[i][0] * 0.125f, acc[i][1] * 0.125f,
                                          acc[i][2] * 0.125f, acc[i][3] * 0.125f);
        *(float4*)(cp + 32 + bc) = make_float4(acc[i][4] * 0.125f, acc[i][5] * 0.125f,
                                               acc[i][6] * 0.125f, acc[i][7] * 0.125f);
    }
}

// ---------------------------------------------------------------------------
// Kernel 2: row softmax over g_S, in place. One block per row of 2048.
// ---------------------------------------------------------------------------
__global__ __launch_bounds__(256) void softmax_kernel() {
    const size_t row = blockIdx.x;
    float* p = g_S + row * (size_t)TT;
    const int tid = threadIdx.x;
    const int warp = tid >> 5, lane = tid & 31;

    float4 v0 = *(const float4*)(p + tid * 8);
    float4 v1 = *(const float4*)(p + tid * 8 + 4);

    float m = fmaxf(fmaxf(fmaxf(v0.x, v0.y), fmaxf(v0.z, v0.w)),
                    fmaxf(fmaxf(v1.x, v1.y), fmaxf(v1.z, v1.w)));
#pragma unroll
    for (int o = 16; o; o >>= 1) m = fmaxf(m, __shfl_xor_sync(0xffffffffu, m, o));

    __shared__ float red[8];
    if (lane == 0) red[warp] = m;
    __syncthreads();
#pragma unroll
    for (int w = 0; w < 8; ++w) m = fmaxf(m, red[w]);

    v0.x = __expf(v0.x - m); v0.y = __expf(v0.y - m);
    v0.z = __expf(v0.z - m); v0.w = __expf(v0.w - m);
    v1.x = __expf(v1.x - m); v1.y = __expf(v1.y - m);
    v1.z = __expf(v1.z - m); v1.w = __expf(v1.w - m);

    float s = v0.x + v0.y + v0.z + v0.w + v1.x + v1.y + v1.z + v1.w;
#pragma unroll
    for (int o = 16; o; o >>= 1) s += __shfl_xor_sync(0xffffffffu, s, o);
    __syncthreads();  // red reuse
    if (lane == 0) red[warp] = s;
    __syncthreads();
    s = 0.f;
#pragma unroll
    for (int w = 0; w < 8; ++w) s += red[w];

    const float inv = 1.0f / s;
    v0.x *= inv; v0.y *= inv; v0.z *= inv; v0.w *= inv;
    v1.x *= inv; v1.y *= inv; v1.z *= inv; v1.w *= inv;
    *(float4*)(p + tid * 8) = v0;
    *(float4*)(p + tid * 8 + 4) = v1;
}

// ---------------------------------------------------------------------------
// Kernel 3: Z[h, r, c] = X_flat[r, :] @ W_h[:, c]   (NN GEMM, K = 1024)
// X_flat = x viewed as [B*T, C]; W_h = weight[h*C:(h+1)*C, :]
// ---------------------------------------------------------------------------
__global__ __launch_bounds__(256, 2) void z_kernel(const float* __restrict__ x,
                                                   const float* __restrict__ wt) {
    const int h    = blockIdx.z;
    const int row0 = blockIdx.y * 128;  // over B*T = 4096
    const int col0 = blockIdx.x * 128;  // over C = 1024

    const float* Ab = x + (size_t)row0 * CC;
    const float* Bb = wt + (size_t)h * CC * CC + col0;
    float* Cb = g_Z + (size_t)h * (BB * TT) * CC + (size_t)row0 * CC + col0;

    __shared__ float As[2][8][128];
    __shared__ float Bs[2][8][128];

    const int tid  = threadIdx.x;
    const int ldr  = tid >> 1;
    const int ldk  = (tid & 1) * 4;
    const int brow = tid >> 5;              // 0..7
    const int bcol = (tid & 31) * 4;        // 0..124
    const int warp = tid >> 5, lane = tid & 31;
    const int wr = (warp & 3) * 32, wc = (warp >> 2) * 64;
    const int ar = (lane >> 3) * 4, bc = (lane & 7) * 4;

    float acc[8][8];
#pragma unroll
    for (int i = 0; i < 8; ++i)
#pragma unroll
        for (int j = 0; j < 8; ++j) acc[i][j] = 0.f;

    {
        float4 a4 = *(const float4*)(Ab + (size_t)ldr * CC + ldk);
        float4 b4 = *(const float4*)(Bb + (size_t)brow * CC + bcol);
        As[0][ldk + 0][ldr] = a4.x; As[0][ldk + 1][ldr] = a4.y;
        As[0][ldk + 2][ldr] = a4.z; As[0][ldk + 3][ldr] = a4.w;
        *(float4*)&Bs[0][brow][bcol] = b4;
    }
    __syncthreads();

    int buf = 0;
    const int NK = CC / 8;  // 128
    for (int kt = 0; kt < NK; ++kt) {
        float4 a4n, b4n;
        if (kt + 1 < NK) {
            a4n = *(const float4*)(Ab + (size_t)ldr * CC + (kt + 1) * 8 + ldk);
            b4n = *(const float4*)(Bb + (size_t)((kt + 1) * 8 + brow) * CC + bcol);
        }
        mma_step(As[buf], Bs[buf], wr, wc, ar, bc, acc);
        if (kt + 1 < NK) {
            const int nb = buf ^ 1;
            As[nb][ldk + 0][ldr] = a4n.x; As[nb][ldk + 1][ldr] = a4n.y;
            As[nb][ldk + 2][ldr] = a4n.z; As[nb][ldk + 3][ldr] = a4n.w;
            *(float4*)&Bs[nb][brow][bcol] = b4n;
            __syncthreads();
            buf = nb;
        }
    }

#pragma unroll
    for (int i = 0; i < 8; ++i) {
        const int r = wr + ar + (i < 4 ? i : i + 12);
        float* cp = Cb + (size_t)r * CC + wc;
        *(float4*)(cp + bc) = make_float4(acc[i][0], acc[i][1], acc[i][2], acc[i][3]);
        *(float4*)(cp + 32 + bc) = make_float4(acc[i][4], acc[i][5], acc[i][6], acc[i][7]);
    }
}

// ---------------------------------------------------------------------------
// Kernel 4: out[b, t, c] = sum_h sum_s P[b,h,t,s] * Z[h, b*T+s, c]
// One GEMM per b with K = NH*T = 32768 (h outer, s inner).
// ---------------------------------------------------------------------------
__global__ __launch_bounds__(256, 2) void out_kernel(float* __restrict__ out) {
    const int b    = blockIdx.z;
    const int row0 = blockIdx.y * 128;  // t tile
    const int col0 = blockIdx.x * 128;  // c tile

    __shared__ float As[2][8][128];
    __shared__ float Bs[2][8][128];

    const int tid  = threadIdx.x;
    const int ldr  = tid >> 1;
    const int ldk  = (tid & 1) * 4;
    const int brow = tid >> 5;
    const int bcol = (tid & 31) * 4;
    const int warp = tid >> 5, lane = tid & 31;
    const int wr = (warp & 3) * 32, wc = (warp >> 2) * 64;
    const int ar = (lane >> 3) * 4, bc = (lane & 7) * 4;

    float acc[8][8];
#pragma unroll
    for (int i = 0; i < 8; ++i)
#pragma unroll
        for (int j = 0; j < 8; ++j) acc[i][j] = 0.f;

    // k-tile pointer helpers: kk = kt*8 ; h = kk>>11 ; s = kk & 2047
    {
        const float* Ap = g_S + ((size_t)((b * NH + 0) * TT) + row0 + ldr) * TT + 0 + ldk;
        const float* Bp = g_Z + ((size_t)((0 * BB + b) * TT) + 0 + brow) * CC + col0 + bcol;
        float4 a4 = *(const float4*)Ap;
        float4 b4 = *(const float4*)Bp;
        As[0][ldk + 0][ldr] = a4.x; As[0][ldk + 1][ldr] = a4.y;
        As[0][ldk + 2][ldr] = a4.z; As[0][ldk + 3][ldr] = a4.w;
        *(float4*)&Bs[0][brow][bcol] = b4;
    }
    __syncthreads();

    int buf = 0;
    const int NK = (NH * TT) / 8;  // 4096
    for (int kt = 0; kt < NK; ++kt) {
        float4 a4n, b4n;
        if (kt + 1 < NK) {
            const int kk = (kt + 1) * 8;
            const int h = kk >> 11;
            const int s = kk & 2047;
            const float* Ap = g_S + ((size_t)((b * NH + h) * TT) + row0 + ldr) * TT + s + ldk;
            const float* Bp = g_Z + ((size_t)((h * BB + b) * TT) + s + brow) * CC + col0 + bcol;
            a4n = *(const float4*)Ap;
            b4n = *(const float4*)Bp;
        }
        mma_step(As[buf], Bs[buf], wr, wc, ar, bc, acc);
        if (kt + 1 < NK) {
            const int nb = buf ^ 1;
            As[nb][ldk + 0][ldr] = a4n.x; As[nb][ldk + 1][ldr] = a4n.y;
            As[nb][ldk + 2][ldr] = a4n.z; As[nb][ldk + 3][ldr] = a4n.w;
            *(float4*)&Bs[nb][brow][bcol] = b4n;
            __syncthreads();
            buf = nb;
        }
    }

#pragma unroll
    for (int i = 0; i < 8; ++i) {
        const int r = wr + ar + (i < 4 ? i : i + 12);
        float* cp = out + ((size_t)(b * TT + row0 + r)) * CC + col0 + wc;
        *(float4*)(cp + bc) = make_float4(acc[i][0], acc[i][1], acc[i][2], acc[i][3]);
        *(float4*)(cp + 32 + bc) = make_float4(acc[i][4], acc[i][5], acc[i][6], acc[i][7]);
    }
}

// ---------------------------------------------------------------------------
extern "C" void kernel_launch(void* const* d_in, const int* in_sizes, int n_in,
                              void* d_out, int out_size) {
    const float* x  = (const float*)d_in[0];   // [2, 2048, 1024]
    const float* wt = (const float*)d_in[1];   // [16384, 1024]
    float* out = (float*)d_out;                // [2, 2048, 1024]

    scores_kernel<<<dim3(TT / 128, TT / 128, BB * NH), 256>>>(x);
    softmax_kernel<<<BB * NH * TT, 256>>>();
    z_kernel<<<dim3(CC / 128, (BB * TT) / 128, NH), 256>>>(x, wt);
    out_kernel<<<dim3(CC / 128, TT / 128, BB), 256>>>(out);
}